// round 6
// baseline (speedup 1.0000x reference)
#include <cuda_runtime.h>
#include <cuda_bf16.h>
#include <cstdint>

// ChamferDistance via z-bucketed exact pruned NN search, warp-uniform scan.
// Stage 1: counting-bucketize each (set,batch) by z into 256 uniform buckets
//          (transformed points (-2x,-2y,-2z,||p||^2), bucket starts).
// Stage 2: one query per thread; each WARP owns 32 z-adjacent queries and
//          scans a warp-uniform candidate range with broadcast __ldg float4
//          loads; sound per-lane early-exit bounds, ballot-driven extension.
// Stage 3: tree reduce.

#define BATCH    16
#define NPTS     4096
#define NBUCK    256
#define ZLO      (-4.6f)
#define ZHI      (4.6f)
#define BW       ((ZHI - ZLO) / NBUCK)
#define INVBW    ((float)NBUCK / (ZHI - ZLO))
#define EXPAND   5                       // initial bucket expansion each side

#define BTHREADS 512
#define SBLOCK   256
#define SBPB     (NPTS / SBLOCK)         // 16 search blocks per (dir,b)
#define NSBLK    (SBPB * BATCH * 2)      // 512
#define FINF     __int_as_float(0x7f800000)

__device__ float4 g_pts[2 * BATCH][NPTS];
__device__ int    g_start[2 * BATCH][NBUCK + 1];
__device__ float  g_bsum[NSBLK];

__device__ __forceinline__ int bucket_of(float z) {
    int b = (int)floorf((z - ZLO) * INVBW);
    return min(max(b, 0), NBUCK - 1);
}

// ---------------- stage 1: bucketize (one global pass, parallel scan) --------
__global__ __launch_bounds__(BTHREADS)
void chamfer_bucketize_kernel(const float* __restrict__ x,
                              const float* __restrict__ y) {
    extern __shared__ float sm[];                 // px | py | pz (48 KB)
    float* px = sm;
    float* py = sm + NPTS;
    float* pz = sm + 2 * NPTS;
    __shared__ int cnt[NBUCK];
    __shared__ int scan[NBUCK];
    __shared__ int off[NBUCK];

    const int b = blockIdx.x, set = blockIdx.y;
    const float* src = (set == 0 ? x : y) + (size_t)b * NPTS * 3;
    const int sb = set * BATCH + b;
    const int tid = threadIdx.x;

    for (int i = tid; i < NBUCK; i += BTHREADS) cnt[i] = 0;
    __syncthreads();

    #pragma unroll
    for (int i = tid; i < NPTS; i += BTHREADS) {
        float a = src[3 * i], c = src[3 * i + 1], d = src[3 * i + 2];
        px[i] = a; py[i] = c; pz[i] = d;
        atomicAdd(&cnt[bucket_of(d)], 1);
    }
    __syncthreads();

    // Inclusive Hillis-Steele scan over 256 counts.
    if (tid < NBUCK) scan[tid] = cnt[tid];
    #pragma unroll
    for (int o = 1; o < NBUCK; o <<= 1) {
        __syncthreads();
        int v = (tid < NBUCK && tid >= o) ? scan[tid - o] : 0;
        __syncthreads();
        if (tid < NBUCK) scan[tid] += v;
    }
    __syncthreads();
    if (tid < NBUCK) {
        int st = scan[tid] - cnt[tid];
        off[tid] = st;
        g_start[sb][tid] = st;
        if (tid == 0) g_start[sb][NBUCK] = NPTS;
    }
    __syncthreads();

    #pragma unroll
    for (int i = tid; i < NPTS; i += BTHREADS) {
        float a = px[i], c = py[i], d = pz[i];
        int pos = atomicAdd(&off[bucket_of(d)], 1);
        g_pts[sb][pos] = make_float4(-2.f * a, -2.f * c, -2.f * d,
                                     fmaf(a, a, fmaf(c, c, d * d)));
    }
}

// ---------------- stage 2: warp-uniform pruned search ------------------------
__device__ __forceinline__ void scan_range(const float4* __restrict__ refs,
                                           int s, int e,          // warp-uniform
                                           float qx, float qy, float qz,
                                           float& bestp) {
    float b0 = bestp, b1 = FINF, b2 = FINF, b3 = FINF;
    int k = s;
    for (; k + 4 <= e; k += 4) {
        float4 f0 = __ldg(&refs[k]);
        float4 f1 = __ldg(&refs[k + 1]);
        float4 f2 = __ldg(&refs[k + 2]);
        float4 f3 = __ldg(&refs[k + 3]);
        b0 = fminf(b0, fmaf(qx, f0.x, fmaf(qy, f0.y, fmaf(qz, f0.z, f0.w))));
        b1 = fminf(b1, fmaf(qx, f1.x, fmaf(qy, f1.y, fmaf(qz, f1.z, f1.w))));
        b2 = fminf(b2, fmaf(qx, f2.x, fmaf(qy, f2.y, fmaf(qz, f2.z, f2.w))));
        b3 = fminf(b3, fmaf(qx, f3.x, fmaf(qy, f3.y, fmaf(qz, f3.z, f3.w))));
    }
    for (; k < e; k++) {
        float4 f0 = __ldg(&refs[k]);
        b0 = fminf(b0, fmaf(qx, f0.x, fmaf(qy, f0.y, fmaf(qz, f0.z, f0.w))));
    }
    bestp = fminf(fminf(b0, b1), fminf(b2, b3));
}

__global__ __launch_bounds__(SBLOCK)
void chamfer_search_kernel() {
    __shared__ float wsum[SBLOCK / 32];
    const int chunk = blockIdx.x, b = blockIdx.y, dir = blockIdx.z;
    const int rsb = (dir == 0 ? 1 : 0) * BATCH + b;
    const int qsb = (dir == 0 ? 0 : 1) * BATCH + b;
    const float4* __restrict__ refs = g_pts[rsb];
    const int* __restrict__ starts = g_start[rsb];
    const int tid = threadIdx.x, lane = tid & 31, wid = tid >> 5;

    const int qi = chunk * SBLOCK + tid;            // coalesced, z-sorted
    float4 qv = __ldg(&g_pts[qsb][qi]);
    const float qx = -0.5f * qv.x;
    const float qy = -0.5f * qv.y;
    const float qz = -0.5f * qv.z;
    const float q2 = qv.w;

    const int qb = bucket_of(qz);
    // Warp-uniform initial bucket range.
    int mn = qb, mx = qb;
    #pragma unroll
    for (int o = 16; o; o >>= 1) {
        mn = min(mn, __shfl_xor_sync(0xFFFFFFFFu, mn, o));
        mx = max(mx, __shfl_xor_sync(0xFFFFFFFFu, mx, o));
    }
    int blo = max(mn - EXPAND, 0);
    int bhi = min(mx + EXPAND, NBUCK - 1);

    float bestp = FINF;                             // min(||r||^2 - 2 q.r)
    scan_range(refs, __ldg(&starts[blo]), __ldg(&starts[bhi + 1]),
               qx, qy, qz, bestp);

    // Ballot-driven sound extension.
    while (true) {
        bool nd = false, nu = false;
        if (blo > 0) {
            float g = fmaxf(qz - (ZLO + (float)blo * BW), 0.f);
            nd = fmaf(g, g, -q2) < bestp;
        }
        if (bhi < NBUCK - 1) {
            float g = fmaxf((ZLO + (float)(bhi + 1) * BW) - qz, 0.f);
            nu = fmaf(g, g, -q2) < bestp;
        }
        unsigned vd = __ballot_sync(0xFFFFFFFFu, nd);
        unsigned vu = __ballot_sync(0xFFFFFFFFu, nu);
        if (vd) {
            blo--;
            scan_range(refs, __ldg(&starts[blo]), __ldg(&starts[blo + 1]),
                       qx, qy, qz, bestp);
        } else if (vu) {
            bhi++;
            scan_range(refs, __ldg(&starts[bhi]), __ldg(&starts[bhi + 1]),
                       qx, qy, qz, bestp);
        } else break;
    }

    float val = q2 + bestp;                         // exact NN sq-dist

    #pragma unroll
    for (int o = 16; o; o >>= 1) val += __shfl_xor_sync(0xFFFFFFFFu, val, o);
    if (lane == 0) wsum[wid] = val;
    __syncthreads();
    if (tid == 0) {
        float s = 0.f;
        #pragma unroll
        for (int i = 0; i < SBLOCK / 32; i++) s += wsum[i];
        g_bsum[(blockIdx.z * BATCH + blockIdx.y) * SBPB + blockIdx.x] = s;
    }
}

// ---------------- stage 3: final reduce --------------------------------------
__global__ __launch_bounds__(256)
void chamfer_final_kernel(float* __restrict__ out) {
    __shared__ float ws[8];
    float s = 0.f;
    for (int i = threadIdx.x; i < NSBLK; i += 256) s += g_bsum[i];
    #pragma unroll
    for (int o = 16; o; o >>= 1) s += __shfl_xor_sync(0xFFFFFFFFu, s, o);
    int lane = threadIdx.x & 31, wid = threadIdx.x >> 5;
    if (lane == 0) ws[wid] = s;
    __syncthreads();
    if (threadIdx.x == 0) {
        float v = 0.f;
        #pragma unroll
        for (int i = 0; i < 8; i++) v += ws[i];
        out[0] = v * (1.0f / ((float)BATCH * (float)NPTS));
    }
}

extern "C" void kernel_launch(void* const* d_in, const int* in_sizes, int n_in,
                              void* d_out, int out_size) {
    const float* x = (const float*)d_in[0];
    const float* y = (const float*)d_in[1];
    float* out = (float*)d_out;

    cudaFuncSetAttribute(chamfer_bucketize_kernel,
                         cudaFuncAttributeMaxDynamicSharedMemorySize,
                         3 * NPTS * (int)sizeof(float));

    chamfer_bucketize_kernel<<<dim3(BATCH, 2), BTHREADS,
                               3 * NPTS * sizeof(float)>>>(x, y);
    chamfer_search_kernel<<<dim3(SBPB, BATCH, 2), SBLOCK>>>();
    chamfer_final_kernel<<<1, 256>>>(out);
}

// round 7
// speedup vs baseline: 1.0667x; 1.0667x over previous
#include <cuda_runtime.h>
#include <cuda_bf16.h>
#include <cstdint>

// ChamferDistance via z-bucketed, block-windowed dense NN search.
// Stage 1: counting-bucketize each (set,batch) by z into 256 uniform buckets,
//          storing transformed points (-2x,-2y,-2z,||p||^2) + bucket starts.
// Stage 2: each block owns 128 consecutive (z-bucket-sorted) queries; loads
//          the block-uniform seed ref window into smem (pair-packed for
//          f32x2 FMA), dense-scans it (broadcast LDS, no divergence), then
//          extends bucket-by-bucket with block-uniform sound early exit.
// Stage 3: tree reduce.

#define BATCH    16
#define NPTS     4096
#define NBUCK    256
#define ZLO      (-4.6f)
#define ZHI      (4.6f)
#define BW       ((ZHI - ZLO) / NBUCK)
#define INVBW    ((float)NBUCK / (ZHI - ZLO))
#define EXPAND   2

#define BTHREADS 512
#define STHREADS 128
#define QPB      128                          // queries per search block
#define SBPB     (NPTS / QPB)                 // 32 blocks per (dir,b)
#define NSBLK    (SBPB * BATCH * 2)           // 1024
#define MAXREF   2048                         // smem ref capacity
#define MAXPAIR  (MAXREF / 2)                 // 1024 pairs (32 KB total)
#define FINF     __int_as_float(0x7f800000)

__device__ float4 g_pts[2 * BATCH][NPTS];
__device__ int    g_start[2 * BATCH][NBUCK + 1];
__device__ float  g_bsum[NSBLK];

__device__ __forceinline__ int bucket_of(float z) {
    int b = (int)floorf((z - ZLO) * INVBW);
    return min(max(b, 0), NBUCK - 1);
}

// ---------- packed f32x2 helpers ----------
__device__ __forceinline__ unsigned long long ffma2(unsigned long long a,
                                                    unsigned long long b,
                                                    unsigned long long c) {
    unsigned long long d;
    asm("fma.rn.f32x2 %0, %1, %2, %3;" : "=l"(d) : "l"(a), "l"(b), "l"(c));
    return d;
}
__device__ __forceinline__ unsigned long long pack2(float lo, float hi) {
    unsigned long long d;
    asm("mov.b64 %0, {%1, %2};" : "=l"(d) : "r"(__float_as_uint(lo)), "r"(__float_as_uint(hi)));
    return d;
}
__device__ __forceinline__ void unpack2(unsigned long long v, float& lo, float& hi) {
    unsigned int l, h;
    asm("mov.b64 {%0, %1}, %2;" : "=r"(l), "=r"(h) : "l"(v));
    lo = __uint_as_float(l);
    hi = __uint_as_float(h);
}

// ---------------- stage 1: bucketize (one global pass, parallel scan) --------
__global__ __launch_bounds__(BTHREADS)
void chamfer_bucketize_kernel(const float* __restrict__ x,
                              const float* __restrict__ y) {
    extern __shared__ float sm[];                 // px | py | pz (48 KB)
    float* px = sm;
    float* py = sm + NPTS;
    float* pz = sm + 2 * NPTS;
    __shared__ int cnt[NBUCK];
    __shared__ int scan[NBUCK];
    __shared__ int off[NBUCK];

    const int b = blockIdx.x, set = blockIdx.y;
    const float* src = (set == 0 ? x : y) + (size_t)b * NPTS * 3;
    const int sb = set * BATCH + b;
    const int tid = threadIdx.x;

    for (int i = tid; i < NBUCK; i += BTHREADS) cnt[i] = 0;
    __syncthreads();
    #pragma unroll
    for (int i = tid; i < NPTS; i += BTHREADS) {
        float a = src[3 * i], c = src[3 * i + 1], d = src[3 * i + 2];
        px[i] = a; py[i] = c; pz[i] = d;
        atomicAdd(&cnt[bucket_of(d)], 1);
    }
    __syncthreads();
    if (tid < NBUCK) scan[tid] = cnt[tid];
    #pragma unroll
    for (int o = 1; o < NBUCK; o <<= 1) {
        __syncthreads();
        int v = (tid < NBUCK && tid >= o) ? scan[tid - o] : 0;
        __syncthreads();
        if (tid < NBUCK) scan[tid] += v;
    }
    __syncthreads();
    if (tid < NBUCK) {
        int st = scan[tid] - cnt[tid];
        off[tid] = st;
        g_start[sb][tid] = st;
        if (tid == 0) g_start[sb][NBUCK] = NPTS;
    }
    __syncthreads();
    #pragma unroll
    for (int i = tid; i < NPTS; i += BTHREADS) {
        float a = px[i], c = py[i], d = pz[i];
        int pos = atomicAdd(&off[bucket_of(d)], 1);
        g_pts[sb][pos] = make_float4(-2.f * a, -2.f * c, -2.f * d,
                                     fmaf(a, a, fmaf(c, c, d * d)));
    }
}

// ---------------- stage 2: block-windowed dense search ------------------------
__device__ __forceinline__ void scan_ldg(const float4* __restrict__ refs,
                                         int s, int e,
                                         float qx, float qy, float qz,
                                         float& bestp) {
    float b0 = bestp, b1 = FINF;
    int k = s;
    for (; k + 2 <= e; k += 2) {
        float4 f0 = __ldg(&refs[k]);
        float4 f1 = __ldg(&refs[k + 1]);
        b0 = fminf(b0, fmaf(qx, f0.x, fmaf(qy, f0.y, fmaf(qz, f0.z, f0.w))));
        b1 = fminf(b1, fmaf(qx, f1.x, fmaf(qy, f1.y, fmaf(qz, f1.z, f1.w))));
    }
    if (k < e) {
        float4 f0 = __ldg(&refs[k]);
        b0 = fminf(b0, fmaf(qx, f0.x, fmaf(qy, f0.y, fmaf(qz, f0.z, f0.w))));
    }
    bestp = fminf(b0, b1);
}

__global__ __launch_bounds__(STHREADS)
void chamfer_search_kernel() {
    __shared__ float4 shA[MAXPAIR];   // (-2x0,-2x1,-2y0,-2y1)
    __shared__ float4 shB[MAXPAIR];   // (-2z0,-2z1, n0,  n1)
    __shared__ int s_bmin, s_bmax;
    __shared__ float wsum[STHREADS / 32];

    const int chunk = blockIdx.x, b = blockIdx.y, dir = blockIdx.z;
    const int rsb = (dir == 0 ? 1 : 0) * BATCH + b;
    const int qsb = (dir == 0 ? 0 : 1) * BATCH + b;
    const float4* __restrict__ refs = g_pts[rsb];
    const int* __restrict__ starts = g_start[rsb];
    const int tid = threadIdx.x;

    const int qi = chunk * QPB + tid;             // consecutive bucket-sorted
    float4 qv = __ldg(&g_pts[qsb][qi]);
    const float qx = -0.5f * qv.x;
    const float qy = -0.5f * qv.y;
    const float qz = -0.5f * qv.z;
    const float q2 = qv.w;
    const int qb = bucket_of(qz);

    if (tid == 0) { s_bmin = NBUCK; s_bmax = -1; }
    __syncthreads();
    atomicMin(&s_bmin, qb);
    atomicMax(&s_bmax, qb);
    __syncthreads();

    int blo = max(s_bmin - EXPAND, 0);
    int bhi = min(s_bmax + EXPAND, NBUCK - 1);
    int s0 = __ldg(&starts[blo]);
    int e0 = __ldg(&starts[bhi + 1]);
    if (e0 - s0 > MAXREF) {                       // safety: drop expansion
        blo = s_bmin; bhi = s_bmax;
        s0 = __ldg(&starts[blo]);
        e0 = __ldg(&starts[bhi + 1]);
    }

    float bestp = FINF;                           // min(||r||^2 - 2 q.r)

    if (e0 - s0 <= MAXREF) {
        // Pack seed refs into smem pair format (cooperative).
        const int R = e0 - s0;
        const int P = (R + 1) >> 1;
        for (int p = tid; p < P; p += STHREADS) {
            int i0 = s0 + 2 * p;
            float4 r0 = __ldg(&refs[i0]);
            float4 r1 = (i0 + 1 < e0) ? __ldg(&refs[i0 + 1])
                                      : make_float4(0.f, 0.f, 0.f, 1e37f);
            shA[p] = make_float4(r0.x, r1.x, r0.y, r1.y);
            shB[p] = make_float4(r0.z, r1.z, r0.w, r1.w);
        }
        __syncthreads();

        const unsigned long long qx2 = pack2(qx, qx);
        const unsigned long long qy2 = pack2(qy, qy);
        const unsigned long long qz2 = pack2(qz, qz);
        const ulonglong2* __restrict__ A64 = reinterpret_cast<const ulonglong2*>(shA);
        const ulonglong2* __restrict__ B64 = reinterpret_cast<const ulonglong2*>(shB);

        float mlo = FINF, mhi = FINF;
        #pragma unroll 4
        for (int j = 0; j < P; j++) {
            ulonglong2 va = A64[j];
            ulonglong2 vb = B64[j];
            unsigned long long t =
                ffma2(qx2, va.x, ffma2(qy2, va.y, ffma2(qz2, vb.x, vb.y)));
            float tl, th;
            unpack2(t, tl, th);
            mlo = fminf(mlo, tl);
            mhi = fminf(mhi, th);
        }
        bestp = fminf(mlo, mhi);
    } else {
        // Pathological fallback: dense broadcast-LDG scan of the seed range.
        scan_ldg(refs, s0, e0, qx, qy, qz, bestp);
    }

    // Block-uniform sound extension, one bucket per round.
    while (true) {
        bool nd = false, nu = false;
        if (blo > 0) {
            float g = fmaxf(qz - (ZLO + (float)blo * BW), 0.f);
            nd = fmaf(g, g, -q2) < bestp;
        }
        if (bhi < NBUCK - 1) {
            float g = fmaxf((ZLO + (float)(bhi + 1) * BW) - qz, 0.f);
            nu = fmaf(g, g, -q2) < bestp;
        }
        int anyd = __syncthreads_or(nd ? 1 : 0);
        int anyu = __syncthreads_or(nu ? 1 : 0);
        if (!anyd && !anyu) break;
        if (anyd) {
            blo--;
            scan_ldg(refs, __ldg(&starts[blo]), __ldg(&starts[blo + 1]),
                     qx, qy, qz, bestp);
        } else {
            bhi++;
            scan_ldg(refs, __ldg(&starts[bhi]), __ldg(&starts[bhi + 1]),
                     qx, qy, qz, bestp);
        }
    }

    float val = q2 + bestp;                       // exact NN sq-dist

    #pragma unroll
    for (int o = 16; o; o >>= 1) val += __shfl_xor_sync(0xFFFFFFFFu, val, o);
    const int lane = tid & 31, wid = tid >> 5;
    if (lane == 0) wsum[wid] = val;
    __syncthreads();
    if (tid == 0) {
        float s = 0.f;
        #pragma unroll
        for (int i = 0; i < STHREADS / 32; i++) s += wsum[i];
        g_bsum[(blockIdx.z * BATCH + blockIdx.y) * SBPB + blockIdx.x] = s;
    }
}

// ---------------- stage 3: final reduce --------------------------------------
__global__ __launch_bounds__(256)
void chamfer_final_kernel(float* __restrict__ out) {
    __shared__ float ws[8];
    float s = 0.f;
    for (int i = threadIdx.x; i < NSBLK; i += 256) s += g_bsum[i];
    #pragma unroll
    for (int o = 16; o; o >>= 1) s += __shfl_xor_sync(0xFFFFFFFFu, s, o);
    int lane = threadIdx.x & 31, wid = threadIdx.x >> 5;
    if (lane == 0) ws[wid] = s;
    __syncthreads();
    if (threadIdx.x == 0) {
        float v = 0.f;
        #pragma unroll
        for (int i = 0; i < 8; i++) v += ws[i];
        out[0] = v * (1.0f / ((float)BATCH * (float)NPTS));
    }
}

extern "C" void kernel_launch(void* const* d_in, const int* in_sizes, int n_in,
                              void* d_out, int out_size) {
    const float* x = (const float*)d_in[0];
    const float* y = (const float*)d_in[1];
    float* out = (float*)d_out;

    cudaFuncSetAttribute(chamfer_bucketize_kernel,
                         cudaFuncAttributeMaxDynamicSharedMemorySize,
                         3 * NPTS * (int)sizeof(float));

    chamfer_bucketize_kernel<<<dim3(BATCH, 2), BTHREADS,
                               3 * NPTS * sizeof(float)>>>(x, y);
    chamfer_search_kernel<<<dim3(SBPB, BATCH, 2), STHREADS>>>();
    chamfer_final_kernel<<<1, 256>>>(out);
}